// round 12
// baseline (speedup 1.0000x reference)
#include <cuda_runtime.h>
#include <cuda_fp16.h>
#include <math.h>
#include <stdint.h>

// Problem constants
#define Bv      2
#define Tv      2048
#define Dv      1024
#define Hv      16
#define HDv     64
#define MAXLEN  2048
#define NBIAS   (2 * MAXLEN - 1)   // 4095
#define BT      (Bv * Tv)          // 4096

// ---------------------------------------------------------------------------
// Scratch (device globals)
// ---------------------------------------------------------------------------
__device__ float  g_bias[4608];             // projected RPE bias (zero-padded)
__device__ __half g_xh[BT * Dv];            // x      (half)
__device__ __half g_wh[3 * Dv * Dv];        // qkv_w  (half)
__device__ __half g_owh[Dv * Dv];           // out_w  (half)
__device__ __half g_qh[BT * Dv];            // Q      [b*T+t][h*64+d]
__device__ __half g_kh[BT * Dv];            // K      [b*T+t][h*64+d]
__device__ __half g_vT[Bv * Hv * HDv * Tv]; // V^T  [(b*16+h)*64+d][token]
__device__ __half g_attnh[BT * Dv];         // attention output (half)

// ---------------------------------------------------------------------------
// PTX helpers (sm_103-base safe: cp.async + mma.sync + ldmatrix)
// ---------------------------------------------------------------------------
__device__ __forceinline__ uint32_t smem_u32(const void* p) {
    uint32_t a;
    asm("{ .reg .u64 t; cvta.to.shared.u64 t, %1; cvt.u32.u64 %0, t; }"
        : "=r"(a) : "l"(p));
    return a;
}
__device__ __forceinline__ void cp_async16(uint32_t saddr, const void* gptr) {
    asm volatile("cp.async.cg.shared.global [%0], [%1], 16;"
                 :: "r"(saddr), "l"(gptr) : "memory");
}
#define CP_COMMIT() asm volatile("cp.async.commit_group;" ::: "memory")
#define CP_WAIT(n)  asm volatile("cp.async.wait_group %0;" :: "n"(n) : "memory")

__device__ __forceinline__ void ldsm_x4(uint32_t r[4], uint32_t addr) {
    asm volatile("ldmatrix.sync.aligned.m8n8.x4.shared.b16 {%0,%1,%2,%3}, [%4];"
                 : "=r"(r[0]), "=r"(r[1]), "=r"(r[2]), "=r"(r[3])
                 : "r"(addr));
}
__device__ __forceinline__ void mma_f16(float c[4], const uint32_t a[4],
                                        const uint32_t b[2]) {
    asm volatile(
        "mma.sync.aligned.m16n8k16.row.col.f32.f16.f16.f32 "
        "{%0,%1,%2,%3}, {%4,%5,%6,%7}, {%8,%9}, {%0,%1,%2,%3};"
        : "+f"(c[0]), "+f"(c[1]), "+f"(c[2]), "+f"(c[3])
        : "r"(a[0]), "r"(a[1]), "r"(a[2]), "r"(a[3]),
          "r"(b[0]), "r"(b[1]));
}
__device__ __forceinline__ uint32_t pack_h2(float lo, float hi) {
    __half2 h = __floats2half2_rn(lo, hi);
    return *(uint32_t*)&h;
}

// ---------------------------------------------------------------------------
// Kernel 0: fused prep — fp32->fp16 converts (x, qkv_w, out_w) + RPE bias
// ---------------------------------------------------------------------------
__global__ void prep_kernel(const float* __restrict__ x,
                            const float* __restrict__ w,
                            const float* __restrict__ ow,
                            const float* __restrict__ rel_pos,
                            const float* __restrict__ rpe_w,
                            __half* __restrict__ xh,
                            __half* __restrict__ wh,
                            __half* __restrict__ owh) {
    if (blockIdx.x < 8192) {
        int u = blockIdx.x * blockDim.x + threadIdx.x;
        const float* src;
        __half* dst;
        int idx;
        if (u < 1048576)       { src = x;  dst = xh;  idx = u; }
        else if (u < 1835008)  { src = w;  dst = wh;  idx = u - 1048576; }
        else                   { src = ow; dst = owh; idx = u - 1835008; }
        int i = idx * 4;
        float4 v = *(const float4*)(src + i);
        uint2 o;
        o.x = pack_h2(v.x, v.y);
        o.y = pack_h2(v.z, v.w);
        *(uint2*)&dst[i] = o;
    } else {
        int wid = threadIdx.x >> 5, lane = threadIdx.x & 31;
        int j = (blockIdx.x - 8192) * 8 + wid;
        if (j >= NBIAS) return;
        float v = rel_pos[j * HDv + lane] * rpe_w[lane]
                + rel_pos[j * HDv + 32 + lane] * rpe_w[32 + lane];
        #pragma unroll
        for (int o = 16; o > 0; o >>= 1) v += __shfl_xor_sync(0xffffffffu, v, o);
        if (lane == 0) g_bias[j] = v;
    }
}

// ---------------------------------------------------------------------------
// fp16 mma.sync GEMM, ldmatrix feed, 3-stage cp.async ring, ONE sync/chunk.
// 128x128 CTA tile, BK=64 halfs, 8 warps (2x4), 2 CTAs/SM.
// ---------------------------------------------------------------------------
#define BKH    64
#define PAG    36
#define TILEU  (128 * PAG)
#define STGU   (2 * TILEU)
#define GNSTG  3
#define GSM_B  (GNSTG * STGU * 4)      // 110592 bytes

template<int MODE>
__global__ void __launch_bounds__(256, 2)
f16_gemm(const __half* __restrict__ A, const __half* __restrict__ W,
         const float* __restrict__ bias, float* __restrict__ Cf,
         __half* __restrict__ qh, __half* __restrict__ kh,
         __half* __restrict__ vT, int M, int N, int K) {
    extern __shared__ uint32_t smu[];
    const uint32_t sbase = smem_u32(smu);
    const int tid  = threadIdx.x;
    const int wid  = tid >> 5;
    const int lane = tid & 31;
    const int q    = lane >> 2;
    const int t    = lane & 3;
    const int warp_m = wid >> 2;
    const int warp_n = wid & 3;
    const int bm = blockIdx.y * 128;
    const int bn = blockIdx.x * 128;
    const int nchunk = K / BKH;        // 16

    const int lr   = lane & 15;
    const int lc   = (lane >> 4) * 4;
    const int brow = (lane & 7) | ((lane >> 4) << 3);
    const int bsub = ((lane >> 3) & 1) * 4;

    float acc[4][4][4];
    #pragma unroll
    for (int mi = 0; mi < 4; ++mi)
        #pragma unroll
        for (int ni = 0; ni < 4; ++ni)
            #pragma unroll
            for (int e = 0; e < 4; ++e) acc[mi][ni][e] = 0.f;

    auto load_chunk = [&](int c, int s) {
        const uint32_t ab = sbase + s * (STGU * 4);
        const uint32_t bb = ab + TILEU * 4;
        #pragma unroll
        for (int i = 0; i < 4; ++i) {
            int idx = tid + 256 * i;
            int row = idx >> 3;
            int cc  = idx & 7;
            uint32_t doff = (uint32_t)(row * PAG + cc * 4) * 4;
            cp_async16(ab + doff, A + (size_t)(bm + row) * K + c * BKH + cc * 8);
            cp_async16(bb + doff, W + (size_t)(bn + row) * K + c * BKH + cc * 8);
        }
    };

    load_chunk(0, 0); CP_COMMIT();
    load_chunk(1, 1); CP_COMMIT();

    uint32_t a_base[4], b_base[2];
    #pragma unroll
    for (int mi = 0; mi < 4; ++mi)
        a_base[mi] = sbase + (uint32_t)((warp_m * 64 + mi * 16 + lr) * PAG + lc) * 4;
    #pragma unroll
    for (int p = 0; p < 2; ++p)
        b_base[p] = sbase + (uint32_t)(TILEU + (warp_n * 32 + p * 16 + brow) * PAG + bsub) * 4;

    int s = 0, sl = 2;                 // consume stage, load stage (c+2)%3
    for (int c = 0; c < nchunk; ++c) {
        if (c + 1 < nchunk) { CP_WAIT(1); } else { CP_WAIT(0); }
        __syncthreads();               // single barrier per chunk

        // refill slot consumed at iter c-1 (protected by the sync above)
        if (c + 2 < nchunk) load_chunk(c + 2, sl);
        CP_COMMIT();

        const uint32_t soff = (uint32_t)(s * STGU * 4);
        #pragma unroll
        for (int ks = 0; ks < 4; ++ks) {
            const uint32_t ko = soff + ks * 32;
            uint32_t af[4][4], bq[2][4];
            #pragma unroll
            for (int mi = 0; mi < 4; ++mi) ldsm_x4(af[mi], a_base[mi] + ko);
            #pragma unroll
            for (int p = 0; p < 2; ++p)   ldsm_x4(bq[p], b_base[p] + ko);
            #pragma unroll
            for (int mi = 0; mi < 4; ++mi)
                #pragma unroll
                for (int ni = 0; ni < 4; ++ni)
                    mma_f16(acc[mi][ni], af[mi], &bq[ni >> 1][(ni & 1) * 2]);
        }

        s  = (s  == 2) ? 0 : s  + 1;
        sl = (sl == 2) ? 0 : sl + 1;
    }

    #pragma unroll
    for (int mi = 0; mi < 4; ++mi) {
        const int row0 = bm + warp_m * 64 + mi * 16 + q;
        #pragma unroll
        for (int ni = 0; ni < 4; ++ni) {
            const int col = bn + warp_n * 32 + ni * 8 + 2 * t;
            const float b0 = bias[col], b1 = bias[col + 1];
            float o00 = acc[mi][ni][0] + b0, o01 = acc[mi][ni][1] + b1;
            float o10 = acc[mi][ni][2] + b0, o11 = acc[mi][ni][3] + b1;
            if (MODE == 0) {
                *(float2*)&Cf[(size_t)row0 * N + col] = make_float2(o00, o01);
                *(float2*)&Cf[(size_t)(row0 + 8) * N + col] = make_float2(o10, o11);
            } else {
                if (bn < 2048) {
                    __half* dst = (bn < 1024) ? qh : kh;
                    int coln = (bn < 1024) ? col : col - 1024;
                    *(uint32_t*)&dst[(size_t)row0 * 1024 + coln] = pack_h2(o00, o01);
                    *(uint32_t*)&dst[(size_t)(row0 + 8) * 1024 + coln] = pack_h2(o10, o11);
                } else {
                    int hd = col - 2048;
                    int h = hd >> 6, d = hd & 63;
                    int bb = row0 >> 11, token = row0 & 2047;
                    __half* base = vT + ((size_t)((bb * 16 + h) * 64 + d)) * 2048 + token;
                    base[0]        = __float2half_rn(o00);
                    base[2048]     = __float2half_rn(o01);
                    base[8]        = __float2half_rn(o10);
                    base[2048 + 8] = __float2half_rn(o11);
                }
            }
        }
    }
}

// ---------------------------------------------------------------------------
// Kernel 3: flash attention with RPE, fp16 mma + ldmatrix.
// 4 warps x 32 q-rows; KT=64; 3-stage K/V ring, ONE sync/iter; 3 CTAs/SM.
// ---------------------------------------------------------------------------
#define QT    128
#define KT    64
#define QPA   36
#define VPA   36
#define FSTG  3
#define OFF_Q   0                          // 128*36 = 4608 u32
#define OFF_K   (OFF_Q + QT * QPA)         // + 3*64*36 = 6912
#define OFF_V   (OFF_K + FSTG * KT * QPA)  // + 6912
#define OFF_BW  (OFF_V + FSTG * HDv * VPA) // + 3*192
#define FSMU    (OFF_BW + FSTG * 192)      // 19008 u32
#define FSM_B   (FSMU * 4)                 // 76032 bytes

__global__ void __launch_bounds__(128, 3)
flash_rpe_f16() {
    extern __shared__ uint32_t smu[];
    const uint32_t sb = smem_u32(smu);
    float* smf = (float*)smu;
    const int b = blockIdx.z, h = blockIdx.y;
    const int qbase = blockIdx.x * QT;
    const int tid = threadIdx.x, wid = tid >> 5, lane = tid & 31;
    const int q = lane >> 2, t = lane & 3;
    const int mb = wid * 32;
    const float scale = 0.125f;

    const int lr   = lane & 15;
    const int lc   = (lane >> 4) * 4;
    const int brow = (lane & 7) | ((lane >> 4) << 3);
    const int bsub = ((lane >> 3) & 1) * 4;

    // ---- Q tile via cp.async (rides in group 0 with kv0) ----
    #pragma unroll
    for (int i = 0; i < 8; ++i) {
        int idx = tid + 128 * i;
        int row = idx >> 3;
        int c8  = idx & 7;
        cp_async16(sb + (uint32_t)(OFF_Q + row * QPA + c8 * 4) * 4,
                   g_qh + (size_t)(b * Tv + qbase + row) * 1024 + h * 64 + c8 * 8);
    }

    auto load_kv = [&](int kt, int s) {
        const int kbase = kt * KT;
        const uint32_t kb = sb + (uint32_t)(OFF_K + s * KT * QPA) * 4;
        const uint32_t vb = sb + (uint32_t)(OFF_V + s * HDv * VPA) * 4;
        #pragma unroll
        for (int i = 0; i < 4; ++i) {
            int idx = tid + 128 * i;
            int row = idx >> 3;
            int c8  = idx & 7;
            cp_async16(kb + (uint32_t)(row * QPA + c8 * 4) * 4,
                       g_kh + (size_t)(b * Tv + kbase + row) * 1024 + h * 64 + c8 * 8);
            cp_async16(vb + (uint32_t)(row * VPA + c8 * 4) * 4,
                       g_vT + (size_t)((b * 16 + h) * 64 + row) * 2048 + kbase + c8 * 8);
        }
        if (tid < 48) {
            int base = kbase - qbase + 1920;
            cp_async16(sb + (uint32_t)(OFF_BW + s * 192 + tid * 4) * 4,
                       &g_bias[base + tid * 4]);
        }
    };

    load_kv(0, 0); CP_COMMIT();
    load_kv(1, 1); CP_COMMIT();

    uint32_t q_base[2];
    #pragma unroll
    for (int mt = 0; mt < 2; ++mt)
        q_base[mt] = sb + (uint32_t)(OFF_Q + (mb + mt * 16 + lr) * QPA + lc) * 4;
    uint32_t k_base[4], v_base[4];
    #pragma unroll
    for (int p = 0; p < 4; ++p) {
        k_base[p] = sb + (uint32_t)(OFF_K + (p * 16 + brow) * QPA + bsub) * 4;
        v_base[p] = sb + (uint32_t)(OFF_V + (p * 16 + brow) * VPA + bsub) * 4;
    }

    float m[4], l[4];
    #pragma unroll
    for (int i = 0; i < 4; ++i) { m[i] = -INFINITY; l[i] = 0.f; }
    float ao[2][8][4];
    #pragma unroll
    for (int mt = 0; mt < 2; ++mt)
        #pragma unroll
        for (int ni = 0; ni < 8; ++ni)
            #pragma unroll
            for (int e = 0; e < 4; ++e) ao[mt][ni][e] = 0.f;

    const int NIT = Tv / KT;   // 32
    int s = 0, sl = 2;
    for (int kt = 0; kt < NIT; ++kt) {
        if (kt < NIT - 1) { CP_WAIT(1); } else { CP_WAIT(0); }
        __syncthreads();               // single barrier per iteration

        if (kt + 2 < NIT) load_kv(kt + 2, sl);
        CP_COMMIT();

        const uint32_t ksoff = (uint32_t)(s * KT * QPA * 4);
        const uint32_t vsoff = (uint32_t)(s * HDv * VPA * 4);
        const float* bw = smf + OFF_BW + s * 192;

        // ---- S = Q K^T : 2 m-tiles share each K fragment ----
        float as_[2][8][4];
        #pragma unroll
        for (int mt = 0; mt < 2; ++mt)
            #pragma unroll
            for (int ni = 0; ni < 8; ++ni)
                #pragma unroll
                for (int e = 0; e < 4; ++e) as_[mt][ni][e] = 0.f;

        #pragma unroll
        for (int ks = 0; ks < 4; ++ks) {
            const uint32_t ko = ks * 32;
            uint32_t af0[4], af1[4];
            ldsm_x4(af0, q_base[0] + ko);
            ldsm_x4(af1, q_base[1] + ko);
            #pragma unroll
            for (int p = 0; p < 4; ++p) {
                uint32_t kq[4];
                ldsm_x4(kq, k_base[p] + ksoff + ko);
                mma_f16(as_[0][2 * p],     af0, &kq[0]);
                mma_f16(as_[0][2 * p + 1], af0, &kq[2]);
                mma_f16(as_[1][2 * p],     af1, &kq[0]);
                mma_f16(as_[1][2 * p + 1], af1, &kq[2]);
            }
        }

        // ---- softmax per m-tile ----
        uint32_t pf[2][8][2];
        #pragma unroll
        for (int mt = 0; mt < 2; ++mt) {
            const int rowb = mb + mt * 16;
            float mx0 = -INFINITY, mx1 = -INFINITY;
            #pragma unroll
            for (int ni = 0; ni < 8; ++ni) {
                const int i0 = ni * 8 + 2 * t - rowb - q + 127;
                as_[mt][ni][0] = fmaf(as_[mt][ni][0], scale, bw[i0]);
                as_[mt][ni][1] = fmaf(as_[mt][ni][1], scale, bw[i0 + 1]);
                as_[mt][ni][2] = fmaf(as_[mt][ni][2], scale, bw[i0 - 8]);
                as_[mt][ni][3] = fmaf(as_[mt][ni][3], scale, bw[i0 - 7]);
                mx0 = fmaxf(mx0, fmaxf(as_[mt][ni][0], as_[mt][ni][1]));
                mx1 = fmaxf(mx1, fmaxf(as_[mt][ni][2], as_[mt][ni][3]));
            }
            #pragma unroll
            for (int off = 1; off <= 2; off <<= 1) {
                mx0 = fmaxf(mx0, __shfl_xor_sync(0xffffffffu, mx0, off));
                mx1 = fmaxf(mx1, __shfl_xor_sync(0xffffffffu, mx1, off));
            }
            const float mn0 = fmaxf(m[2 * mt], mx0);
            const float mn1 = fmaxf(m[2 * mt + 1], mx1);
            const float c0 = __expf(m[2 * mt] - mn0);
            const float c1 = __expf(m[2 * mt + 1] - mn1);
            m[2 * mt] = mn0; m[2 * mt + 1] = mn1;

            float rs0 = 0.f, rs1 = 0.f;
            #pragma unroll
            for (int ni = 0; ni < 8; ++ni) {
                float p0 = __expf(as_[mt][ni][0] - mn0);
                float p1 = __expf(as_[mt][ni][1] - mn0);
                float p2 = __expf(as_[mt][ni][2] - mn1);
                float p3 = __expf(as_[mt][ni][3] - mn1);
                rs0 += p0 + p1; rs1 += p2 + p3;
                pf[mt][ni][0] = pack_h2(p0, p1);
                pf[mt][ni][1] = pack_h2(p2, p3);
            }
            #pragma unroll
            for (int off = 1; off <= 2; off <<= 1) {
                rs0 += __shfl_xor_sync(0xffffffffu, rs0, off);
                rs1 += __shfl_xor_sync(0xffffffffu, rs1, off);
            }
            l[2 * mt]     = l[2 * mt] * c0 + rs0;
            l[2 * mt + 1] = l[2 * mt + 1] * c1 + rs1;
            #pragma unroll
            for (int ni = 0; ni < 8; ++ni) {
                ao[mt][ni][0] *= c0; ao[mt][ni][1] *= c0;
                ao[mt][ni][2] *= c1; ao[mt][ni][3] *= c1;
            }
        }

        // ---- O += P @ V : V fragments shared across both m-tiles ----
        #pragma unroll
        for (int ks = 0; ks < 4; ++ks) {
            const uint32_t ko = ks * 32;
            uint32_t a0[4], a1[4];
            a0[0] = pf[0][2 * ks][0];     a0[1] = pf[0][2 * ks][1];
            a0[2] = pf[0][2 * ks + 1][0]; a0[3] = pf[0][2 * ks + 1][1];
            a1[0] = pf[1][2 * ks][0];     a1[1] = pf[1][2 * ks][1];
            a1[2] = pf[1][2 * ks + 1][0]; a1[3] = pf[1][2 * ks + 1][1];
            #pragma unroll
            for (int p = 0; p < 4; ++p) {
                uint32_t vq[4];
                ldsm_x4(vq, v_base[p] + vsoff + ko);
                mma_f16(ao[0][2 * p],     a0, &vq[0]);
                mma_f16(ao[0][2 * p + 1], a0, &vq[2]);
                mma_f16(ao[1][2 * p],     a1, &vq[0]);
                mma_f16(ao[1][2 * p + 1], a1, &vq[2]);
            }
        }

        s  = (s  == 2) ? 0 : s  + 1;
        sl = (sl == 2) ? 0 : sl + 1;
    }

    // ---- normalize, write half attn ----
    #pragma unroll
    for (int mt = 0; mt < 2; ++mt) {
        const float inv0 = 1.f / l[2 * mt];
        const float inv1 = 1.f / l[2 * mt + 1];
        const int r0 = qbase + mb + mt * 16 + q;
        #pragma unroll
        for (int ni = 0; ni < 8; ++ni) {
            const int col = h * HDv + ni * 8 + 2 * t;
            *(uint32_t*)&g_attnh[(size_t)(b * Tv + r0) * Dv + col]
                = pack_h2(ao[mt][ni][0] * inv0, ao[mt][ni][1] * inv0);
            *(uint32_t*)&g_attnh[(size_t)(b * Tv + r0 + 8) * Dv + col]
                = pack_h2(ao[mt][ni][2] * inv1, ao[mt][ni][3] * inv1);
        }
    }
}

// ---------------------------------------------------------------------------
// Launcher
// ---------------------------------------------------------------------------
extern "C" void kernel_launch(void* const* d_in, const int* in_sizes, int n_in,
                              void* d_out, int out_size) {
    const float* x       = (const float*)d_in[0];
    const float* qkv_w   = (const float*)d_in[1];
    const float* qkv_b   = (const float*)d_in[2];
    const float* out_w   = (const float*)d_in[3];
    const float* out_b   = (const float*)d_in[4];
    const float* rel_pos = (const float*)d_in[5];
    const float* rpe_w   = (const float*)d_in[6];
    float* out = (float*)d_out;

    __half *xh, *wh, *owh, *qh, *kh, *vT, *attnh;
    cudaGetSymbolAddress((void**)&xh,    g_xh);
    cudaGetSymbolAddress((void**)&wh,    g_wh);
    cudaGetSymbolAddress((void**)&owh,   g_owh);
    cudaGetSymbolAddress((void**)&qh,    g_qh);
    cudaGetSymbolAddress((void**)&kh,    g_kh);
    cudaGetSymbolAddress((void**)&vT,    g_vT);
    cudaGetSymbolAddress((void**)&attnh, g_attnh);

    cudaFuncSetAttribute(f16_gemm<0>,
                         cudaFuncAttributeMaxDynamicSharedMemorySize, GSM_B);
    cudaFuncSetAttribute(f16_gemm<1>,
                         cudaFuncAttributeMaxDynamicSharedMemorySize, GSM_B);
    cudaFuncSetAttribute(flash_rpe_f16,
                         cudaFuncAttributeMaxDynamicSharedMemorySize, FSM_B);

    // 0) fused converts + RPE bias projection
    prep_kernel<<<8704, 256>>>(x, qkv_w, out_w, rel_pos, rpe_w, xh, wh, owh);

    // 1) QKV projection -> Q,K (half) + V transposed (half)
    {
        dim3 grid(3 * Dv / 128, BT / 128);
        f16_gemm<1><<<grid, 256, GSM_B>>>(xh, wh, qkv_b, nullptr,
                                          qh, kh, vT, BT, 3 * Dv, Dv);
    }

    // 2) flash attention with RPE (3-stage ring, 1 sync/iter)
    {
        dim3 grid(Tv / QT, Hv, Bv);
        flash_rpe_f16<<<grid, 128, FSM_B>>>();
    }

    // 3) output projection -> fp32 out
    {
        dim3 grid(Dv / 128, BT / 128);
        f16_gemm<0><<<grid, 256, GSM_B>>>(attnh, owh, out_b, out,
                                          nullptr, nullptr, nullptr,
                                          BT, Dv, Dv);
    }
}

// round 14
// speedup vs baseline: 1.0801x; 1.0801x over previous
#include <cuda_runtime.h>
#include <cuda_fp16.h>
#include <math.h>
#include <stdint.h>

// Problem constants
#define Bv      2
#define Tv      2048
#define Dv      1024
#define Hv      16
#define HDv     64
#define MAXLEN  2048
#define NBIAS   (2 * MAXLEN - 1)   // 4095
#define BT      (Bv * Tv)          // 4096

// ---------------------------------------------------------------------------
// Scratch (device globals)
// ---------------------------------------------------------------------------
__device__ float  g_bias[4608];             // projected RPE bias * log2(e)
__device__ __half g_xh[BT * Dv];            // x      (half)
__device__ __half g_wh[3 * Dv * Dv];        // qkv_w  (half)
__device__ __half g_owh[Dv * Dv];           // out_w  (half)
__device__ __half g_qh[BT * Dv];            // Q      [b*T+t][h*64+d]
__device__ __half g_kh[BT * Dv];            // K      [b*T+t][h*64+d]
__device__ __half g_vT[Bv * Hv * HDv * Tv]; // V^T  [(b*16+h)*64+d][token]
__device__ __half g_attnh[BT * Dv];         // attention output (half)

// ---------------------------------------------------------------------------
// PTX helpers (sm_103-base safe: cp.async + mma.sync + ldmatrix)
// ---------------------------------------------------------------------------
__device__ __forceinline__ uint32_t smem_u32(const void* p) {
    uint32_t a;
    asm("{ .reg .u64 t; cvta.to.shared.u64 t, %1; cvt.u32.u64 %0, t; }"
        : "=r"(a) : "l"(p));
    return a;
}
__device__ __forceinline__ void cp_async16(uint32_t saddr, const void* gptr) {
    asm volatile("cp.async.cg.shared.global [%0], [%1], 16;"
                 :: "r"(saddr), "l"(gptr) : "memory");
}
#define CP_COMMIT() asm volatile("cp.async.commit_group;" ::: "memory")
#define CP_WAIT(n)  asm volatile("cp.async.wait_group %0;" :: "n"(n) : "memory")

__device__ __forceinline__ void ldsm_x4(uint32_t r[4], uint32_t addr) {
    asm volatile("ldmatrix.sync.aligned.m8n8.x4.shared.b16 {%0,%1,%2,%3}, [%4];"
                 : "=r"(r[0]), "=r"(r[1]), "=r"(r[2]), "=r"(r[3])
                 : "r"(addr));
}
__device__ __forceinline__ void mma_f16(float c[4], const uint32_t a[4],
                                        const uint32_t b[2]) {
    asm volatile(
        "mma.sync.aligned.m16n8k16.row.col.f32.f16.f16.f32 "
        "{%0,%1,%2,%3}, {%4,%5,%6,%7}, {%8,%9}, {%0,%1,%2,%3};"
        : "+f"(c[0]), "+f"(c[1]), "+f"(c[2]), "+f"(c[3])
        : "r"(a[0]), "r"(a[1]), "r"(a[2]), "r"(a[3]),
          "r"(b[0]), "r"(b[1]));
}
__device__ __forceinline__ uint32_t pack_h2(float lo, float hi) {
    __half2 h = __floats2half2_rn(lo, hi);
    return *(uint32_t*)&h;
}
// single-MUFU exp2 (EX2.approx)
__device__ __forceinline__ float ex2(float x) {
    float r;
    asm("ex2.approx.f32 %0, %1;" : "=f"(r) : "f"(x));
    return r;
}

// ---------------------------------------------------------------------------
// Kernel 0: fused prep — fp32->fp16 converts + RPE bias (pre-scaled by log2e)
// ---------------------------------------------------------------------------
__global__ void prep_kernel(const float* __restrict__ x,
                            const float* __restrict__ w,
                            const float* __restrict__ ow,
                            const float* __restrict__ rel_pos,
                            const float* __restrict__ rpe_w,
                            __half* __restrict__ xh,
                            __half* __restrict__ wh,
                            __half* __restrict__ owh) {
    if (blockIdx.x < 8192) {
        int u = blockIdx.x * blockDim.x + threadIdx.x;
        const float* src;
        __half* dst;
        int idx;
        if (u < 1048576)       { src = x;  dst = xh;  idx = u; }
        else if (u < 1835008)  { src = w;  dst = wh;  idx = u - 1048576; }
        else                   { src = ow; dst = owh; idx = u - 1835008; }
        int i = idx * 4;
        float4 v = *(const float4*)(src + i);
        uint2 o;
        o.x = pack_h2(v.x, v.y);
        o.y = pack_h2(v.z, v.w);
        *(uint2*)&dst[i] = o;
    } else {
        int wid = threadIdx.x >> 5, lane = threadIdx.x & 31;
        int j = (blockIdx.x - 8192) * 8 + wid;
        if (j >= NBIAS) return;
        float v = rel_pos[j * HDv + lane] * rpe_w[lane]
                + rel_pos[j * HDv + 32 + lane] * rpe_w[32 + lane];
        #pragma unroll
        for (int o = 16; o > 0; o >>= 1) v += __shfl_xor_sync(0xffffffffu, v, o);
        if (lane == 0) g_bias[j] = v * 1.44269504f;   // * log2(e)
    }
}

// ---------------------------------------------------------------------------
// fp16 mma.sync GEMM, ldmatrix feed, 3-stage cp.async ring, ONE sync/chunk.
// ---------------------------------------------------------------------------
#define BKH    64
#define PAG    36
#define TILEU  (128 * PAG)
#define STGU   (2 * TILEU)
#define GNSTG  3
#define GSM_B  (GNSTG * STGU * 4)      // 110592 bytes

template<int MODE>
__global__ void __launch_bounds__(256, 2)
f16_gemm(const __half* __restrict__ A, const __half* __restrict__ W,
         const float* __restrict__ bias, float* __restrict__ Cf,
         __half* __restrict__ qh, __half* __restrict__ kh,
         __half* __restrict__ vT, int M, int N, int K) {
    extern __shared__ uint32_t smu[];
    const uint32_t sbase = smem_u32(smu);
    const int tid  = threadIdx.x;
    const int wid  = tid >> 5;
    const int lane = tid & 31;
    const int q    = lane >> 2;
    const int t    = lane & 3;
    const int warp_m = wid >> 2;
    const int warp_n = wid & 3;
    const int bm = blockIdx.y * 128;
    const int bn = blockIdx.x * 128;
    const int nchunk = K / BKH;        // 16

    const int lr   = lane & 15;
    const int lc   = (lane >> 4) * 4;
    const int brow = (lane & 7) | ((lane >> 4) << 3);
    const int bsub = ((lane >> 3) & 1) * 4;

    float acc[4][4][4];
    #pragma unroll
    for (int mi = 0; mi < 4; ++mi)
        #pragma unroll
        for (int ni = 0; ni < 4; ++ni)
            #pragma unroll
            for (int e = 0; e < 4; ++e) acc[mi][ni][e] = 0.f;

    auto load_chunk = [&](int c, int s) {
        const uint32_t ab = sbase + s * (STGU * 4);
        const uint32_t bb = ab + TILEU * 4;
        #pragma unroll
        for (int i = 0; i < 4; ++i) {
            int idx = tid + 256 * i;
            int row = idx >> 3;
            int cc  = idx & 7;
            uint32_t doff = (uint32_t)(row * PAG + cc * 4) * 4;
            cp_async16(ab + doff, A + (size_t)(bm + row) * K + c * BKH + cc * 8);
            cp_async16(bb + doff, W + (size_t)(bn + row) * K + c * BKH + cc * 8);
        }
    };

    load_chunk(0, 0); CP_COMMIT();
    load_chunk(1, 1); CP_COMMIT();

    uint32_t a_base[4], b_base[2];
    #pragma unroll
    for (int mi = 0; mi < 4; ++mi)
        a_base[mi] = sbase + (uint32_t)((warp_m * 64 + mi * 16 + lr) * PAG + lc) * 4;
    #pragma unroll
    for (int p = 0; p < 2; ++p)
        b_base[p] = sbase + (uint32_t)(TILEU + (warp_n * 32 + p * 16 + brow) * PAG + bsub) * 4;

    int s = 0, sl = 2;
    for (int c = 0; c < nchunk; ++c) {
        if (c + 1 < nchunk) { CP_WAIT(1); } else { CP_WAIT(0); }
        __syncthreads();

        if (c + 2 < nchunk) load_chunk(c + 2, sl);
        CP_COMMIT();

        const uint32_t soff = (uint32_t)(s * STGU * 4);
        #pragma unroll
        for (int ks = 0; ks < 4; ++ks) {
            const uint32_t ko = soff + ks * 32;
            uint32_t af[4][4], bq[2][4];
            #pragma unroll
            for (int mi = 0; mi < 4; ++mi) ldsm_x4(af[mi], a_base[mi] + ko);
            #pragma unroll
            for (int p = 0; p < 2; ++p)   ldsm_x4(bq[p], b_base[p] + ko);
            #pragma unroll
            for (int mi = 0; mi < 4; ++mi)
                #pragma unroll
                for (int ni = 0; ni < 4; ++ni)
                    mma_f16(acc[mi][ni], af[mi], &bq[ni >> 1][(ni & 1) * 2]);
        }

        s  = (s  == 2) ? 0 : s  + 1;
        sl = (sl == 2) ? 0 : sl + 1;
    }

    #pragma unroll
    for (int mi = 0; mi < 4; ++mi) {
        const int row0 = bm + warp_m * 64 + mi * 16 + q;
        #pragma unroll
        for (int ni = 0; ni < 4; ++ni) {
            const int col = bn + warp_n * 32 + ni * 8 + 2 * t;
            const float b0 = bias[col], b1 = bias[col + 1];
            float o00 = acc[mi][ni][0] + b0, o01 = acc[mi][ni][1] + b1;
            float o10 = acc[mi][ni][2] + b0, o11 = acc[mi][ni][3] + b1;
            if (MODE == 0) {
                *(float2*)&Cf[(size_t)row0 * N + col] = make_float2(o00, o01);
                *(float2*)&Cf[(size_t)(row0 + 8) * N + col] = make_float2(o10, o11);
            } else {
                if (bn < 2048) {
                    __half* dst = (bn < 1024) ? qh : kh;
                    int coln = (bn < 1024) ? col : col - 1024;
                    *(uint32_t*)&dst[(size_t)row0 * 1024 + coln] = pack_h2(o00, o01);
                    *(uint32_t*)&dst[(size_t)(row0 + 8) * 1024 + coln] = pack_h2(o10, o11);
                } else {
                    int hd = col - 2048;
                    int h = hd >> 6, d = hd & 63;
                    int bb = row0 >> 11, token = row0 & 2047;
                    __half* base = vT + ((size_t)((bb * 16 + h) * 64 + d)) * 2048 + token;
                    base[0]        = __float2half_rn(o00);
                    base[2048]     = __float2half_rn(o01);
                    base[8]        = __float2half_rn(o10);
                    base[2048 + 8] = __float2half_rn(o11);
                }
            }
        }
    }
}

// ---------------------------------------------------------------------------
// Kernel 3: flash attention with RPE, fp16 mma + ldmatrix.
// 4 warps x 32 q-rows; KT=64; 2-stage K/V ring; 3 CTAs/SM.
// MAX-FREE softmax: scores bounded -> ex2 directly, no rescaling;
// l accumulated per-thread, reduced once after the loop.
// ---------------------------------------------------------------------------
#define QT    128
#define KT    64
#define QPA   36
#define VPA   36
#define OFF_Q   0
#define OFF_K   (OFF_Q + QT * QPA)
#define OFF_V   (OFF_K + 2 * KT * QPA)
#define OFF_BW  (OFF_V + 2 * HDv * VPA)
#define FSMU    (OFF_BW + 2 * 192)
#define FSM_B   (FSMU * 4)               // 56832 bytes

__global__ void __launch_bounds__(128, 3)
flash_rpe_f16() {
    extern __shared__ uint32_t smu[];
    const uint32_t sb = smem_u32(smu);
    float* smf = (float*)smu;
    const int b = blockIdx.z, h = blockIdx.y;
    const int qbase = blockIdx.x * QT;
    const int tid = threadIdx.x, wid = tid >> 5, lane = tid & 31;
    const int q = lane >> 2, t = lane & 3;
    const int mb = wid * 32;
    const float scale2 = 0.125f * 1.44269504f;   // scale * log2(e)

    const int lr   = lane & 15;
    const int lc   = (lane >> 4) * 4;
    const int brow = (lane & 7) | ((lane >> 4) << 3);
    const int bsub = ((lane >> 3) & 1) * 4;

    // ---- Q tile via cp.async (rides in group 0 with kv0) ----
    #pragma unroll
    for (int i = 0; i < 8; ++i) {
        int idx = tid + 128 * i;
        int row = idx >> 3;
        int c8  = idx & 7;
        cp_async16(sb + (uint32_t)(OFF_Q + row * QPA + c8 * 4) * 4,
                   g_qh + (size_t)(b * Tv + qbase + row) * 1024 + h * 64 + c8 * 8);
    }

    auto load_kv = [&](int kt, int s) {
        const int kbase = kt * KT;
        const uint32_t kb = sb + (uint32_t)(OFF_K + s * KT * QPA) * 4;
        const uint32_t vb = sb + (uint32_t)(OFF_V + s * HDv * VPA) * 4;
        #pragma unroll
        for (int i = 0; i < 4; ++i) {
            int idx = tid + 128 * i;
            int row = idx >> 3;
            int c8  = idx & 7;
            cp_async16(kb + (uint32_t)(row * QPA + c8 * 4) * 4,
                       g_kh + (size_t)(b * Tv + kbase + row) * 1024 + h * 64 + c8 * 8);
            cp_async16(vb + (uint32_t)(row * VPA + c8 * 4) * 4,
                       g_vT + (size_t)((b * 16 + h) * 64 + row) * 2048 + kbase + c8 * 8);
        }
        if (tid < 48) {
            int base = kbase - qbase + 1920;
            cp_async16(sb + (uint32_t)(OFF_BW + s * 192 + tid * 4) * 4,
                       &g_bias[base + tid * 4]);
        }
    };

    load_kv(0, 0); CP_COMMIT();
    load_kv(1, 1); CP_COMMIT();

    uint32_t q_base[2];
    #pragma unroll
    for (int mt = 0; mt < 2; ++mt)
        q_base[mt] = sb + (uint32_t)(OFF_Q + (mb + mt * 16 + lr) * QPA + lc) * 4;
    uint32_t k_base[4], v_base[4];
    #pragma unroll
    for (int p = 0; p < 4; ++p) {
        k_base[p] = sb + (uint32_t)(OFF_K + (p * 16 + brow) * QPA + bsub) * 4;
        v_base[p] = sb + (uint32_t)(OFF_V + (p * 16 + brow) * VPA + bsub) * 4;
    }

    // l partials per thread: [2*mt + rowhalf]; reduced across quad at end
    float l[4] = {0.f, 0.f, 0.f, 0.f};
    float ao[2][8][4];
    #pragma unroll
    for (int mt = 0; mt < 2; ++mt)
        #pragma unroll
        for (int ni = 0; ni < 8; ++ni)
            #pragma unroll
            for (int e = 0; e < 4; ++e) ao[mt][ni][e] = 0.f;

    const int NIT = Tv / KT;   // 32
    for (int kt = 0; kt < NIT; ++kt) {
        const int s = kt & 1;
        if (kt < NIT - 1) { CP_WAIT(1); } else { CP_WAIT(0); }
        __syncthreads();

        const uint32_t ksoff = (uint32_t)(s * KT * QPA * 4);
        const uint32_t vsoff = (uint32_t)(s * HDv * VPA * 4);
        const float* bw = smf + OFF_BW + s * 192;

        // ---- S = Q K^T : 2 m-tiles share each K fragment ----
        float as_[2][8][4];
        #pragma unroll
        for (int mt = 0; mt < 2; ++mt)
            #pragma unroll
            for (int ni = 0; ni < 8; ++ni)
                #pragma unroll
                for (int e = 0; e < 4; ++e) as_[mt][ni][e] = 0.f;

        #pragma unroll
        for (int ks = 0; ks < 4; ++ks) {
            const uint32_t ko = ks * 32;
            uint32_t af0[4], af1[4];
            ldsm_x4(af0, q_base[0] + ko);
            ldsm_x4(af1, q_base[1] + ko);
            #pragma unroll
            for (int p = 0; p < 4; ++p) {
                uint32_t kq[4];
                ldsm_x4(kq, k_base[p] + ksoff + ko);
                mma_f16(as_[0][2 * p],     af0, &kq[0]);
                mma_f16(as_[0][2 * p + 1], af0, &kq[2]);
                mma_f16(as_[1][2 * p],     af1, &kq[0]);
                mma_f16(as_[1][2 * p + 1], af1, &kq[2]);
            }
        }

        // ---- max-free softmax: p = ex2(s*scale2 + bias2) ----
        uint32_t pf[2][8][2];
        #pragma unroll
        for (int mt = 0; mt < 2; ++mt) {
            const int rowb = mb + mt * 16;
            float rs0 = 0.f, rs1 = 0.f;
            #pragma unroll
            for (int ni = 0; ni < 8; ++ni) {
                const int i0 = ni * 8 + 2 * t - rowb - q + 127;
                float p0 = ex2(fmaf(as_[mt][ni][0], scale2, bw[i0]));
                float p1 = ex2(fmaf(as_[mt][ni][1], scale2, bw[i0 + 1]));
                float p2 = ex2(fmaf(as_[mt][ni][2], scale2, bw[i0 - 8]));
                float p3 = ex2(fmaf(as_[mt][ni][3], scale2, bw[i0 - 7]));
                rs0 += p0 + p1; rs1 += p2 + p3;
                pf[mt][ni][0] = pack_h2(p0, p1);
                pf[mt][ni][1] = pack_h2(p2, p3);
            }
            l[2 * mt]     += rs0;
            l[2 * mt + 1] += rs1;
        }

        // ---- O += P @ V : V fragments shared across both m-tiles ----
        #pragma unroll
        for (int ks = 0; ks < 4; ++ks) {
            const uint32_t ko = ks * 32;
            uint32_t a0[4], a1[4];
            a0[0] = pf[0][2 * ks][0];     a0[1] = pf[0][2 * ks][1];
            a0[2] = pf[0][2 * ks + 1][0]; a0[3] = pf[0][2 * ks + 1][1];
            a1[0] = pf[1][2 * ks][0];     a1[1] = pf[1][2 * ks][1];
            a1[2] = pf[1][2 * ks + 1][0]; a1[3] = pf[1][2 * ks + 1][1];
            #pragma unroll
            for (int p = 0; p < 4; ++p) {
                uint32_t vq[4];
                ldsm_x4(vq, v_base[p] + vsoff + ko);
                mma_f16(ao[0][2 * p],     a0, &vq[0]);
                mma_f16(ao[0][2 * p + 1], a0, &vq[2]);
                mma_f16(ao[1][2 * p],     a1, &vq[0]);
                mma_f16(ao[1][2 * p + 1], a1, &vq[2]);
            }
        }

        __syncthreads();
        if (kt + 2 < NIT) { load_kv(kt + 2, s); CP_COMMIT(); }
    }

    // ---- reduce l across the quad (once), normalize, write half attn ----
    #pragma unroll
    for (int i = 0; i < 4; ++i) {
        #pragma unroll
        for (int off = 1; off <= 2; off <<= 1)
            l[i] += __shfl_xor_sync(0xffffffffu, l[i], off);
    }
    #pragma unroll
    for (int mt = 0; mt < 2; ++mt) {
        const float inv0 = 1.f / l[2 * mt];
        const float inv1 = 1.f / l[2 * mt + 1];
        const int r0 = qbase + mb + mt * 16 + q;
        #pragma unroll
        for (int ni = 0; ni < 8; ++ni) {
            const int col = h * HDv + ni * 8 + 2 * t;
            *(uint32_t*)&g_attnh[(size_t)(b * Tv + r0) * Dv + col]
                = pack_h2(ao[mt][ni][0] * inv0, ao[mt][ni][1] * inv0);
            *(uint32_t*)&g_attnh[(size_t)(b * Tv + r0 + 8) * Dv + col]
                = pack_h2(ao[mt][ni][2] * inv1, ao[mt][ni][3] * inv1);
        }
    }
}

// ---------------------------------------------------------------------------
// Launcher
// ---------------------------------------------------------------------------
extern "C" void kernel_launch(void* const* d_in, const int* in_sizes, int n_in,
                              void* d_out, int out_size) {
    const float* x       = (const float*)d_in[0];
    const float* qkv_w   = (const float*)d_in[1];
    const float* qkv_b   = (const float*)d_in[2];
    const float* out_w   = (const float*)d_in[3];
    const float* out_b   = (const float*)d_in[4];
    const float* rel_pos = (const float*)d_in[5];
    const float* rpe_w   = (const float*)d_in[6];
    float* out = (float*)d_out;

    __half *xh, *wh, *owh, *qh, *kh, *vT, *attnh;
    cudaGetSymbolAddress((void**)&xh,    g_xh);
    cudaGetSymbolAddress((void**)&wh,    g_wh);
    cudaGetSymbolAddress((void**)&owh,   g_owh);
    cudaGetSymbolAddress((void**)&qh,    g_qh);
    cudaGetSymbolAddress((void**)&kh,    g_kh);
    cudaGetSymbolAddress((void**)&vT,    g_vT);
    cudaGetSymbolAddress((void**)&attnh, g_attnh);

    cudaFuncSetAttribute(f16_gemm<0>,
                         cudaFuncAttributeMaxDynamicSharedMemorySize, GSM_B);
    cudaFuncSetAttribute(f16_gemm<1>,
                         cudaFuncAttributeMaxDynamicSharedMemorySize, GSM_B);
    cudaFuncSetAttribute(flash_rpe_f16,
                         cudaFuncAttributeMaxDynamicSharedMemorySize, FSM_B);

    // 0) fused converts + RPE bias projection (bias pre-scaled by log2e)
    prep_kernel<<<8704, 256>>>(x, qkv_w, out_w, rel_pos, rpe_w, xh, wh, owh);

    // 1) QKV projection -> Q,K (half) + V transposed (half)
    {
        dim3 grid(3 * Dv / 128, BT / 128);
        f16_gemm<1><<<grid, 256, GSM_B>>>(xh, wh, qkv_b, nullptr,
                                          qh, kh, vT, BT, 3 * Dv, Dv);
    }

    // 2) flash attention with RPE (max-free ex2 softmax)
    {
        dim3 grid(Tv / QT, Hv, Bv);
        flash_rpe_f16<<<grid, 128, FSM_B>>>();
    }

    // 3) output projection -> fp32 out
    {
        dim3 grid(Dv / 128, BT / 128);
        f16_gemm<0><<<grid, 256, GSM_B>>>(attnh, owh, out_b, out,
                                          nullptr, nullptr, nullptr,
                                          BT, Dv, Dv);
    }
}

// round 15
// speedup vs baseline: 1.0850x; 1.0046x over previous
#include <cuda_runtime.h>
#include <cuda_fp16.h>
#include <math.h>
#include <stdint.h>

// Problem constants
#define Bv      2
#define Tv      2048
#define Dv      1024
#define Hv      16
#define HDv     64
#define MAXLEN  2048
#define NBIAS   (2 * MAXLEN - 1)   // 4095
#define BT      (Bv * Tv)          // 4096

// ---------------------------------------------------------------------------
// Scratch (device globals)
// ---------------------------------------------------------------------------
__device__ float  g_bias[4608];             // projected RPE bias * log2(e)
__device__ __half g_xh[BT * Dv];            // x      (half)
__device__ __half g_wh[3 * Dv * Dv];        // qkv_w  (half)
__device__ __half g_owh[Dv * Dv];           // out_w  (half)
__device__ __half g_qh[BT * Dv];            // Q      [b*T+t][h*64+d]
__device__ __half g_kh[BT * Dv];            // K      [b*T+t][h*64+d]
__device__ __half g_vT[Bv * Hv * HDv * Tv]; // V^T  [(b*16+h)*64+d][token]
__device__ __half g_attnh[BT * Dv];         // attention output (half)

// ---------------------------------------------------------------------------
// PTX helpers (sm_103-base safe: cp.async + mma.sync + ldmatrix)
// ---------------------------------------------------------------------------
__device__ __forceinline__ uint32_t smem_u32(const void* p) {
    uint32_t a;
    asm("{ .reg .u64 t; cvta.to.shared.u64 t, %1; cvt.u32.u64 %0, t; }"
        : "=r"(a) : "l"(p));
    return a;
}
__device__ __forceinline__ void cp_async16(uint32_t saddr, const void* gptr) {
    asm volatile("cp.async.cg.shared.global [%0], [%1], 16;"
                 :: "r"(saddr), "l"(gptr) : "memory");
}
#define CP_COMMIT() asm volatile("cp.async.commit_group;" ::: "memory")
#define CP_WAIT(n)  asm volatile("cp.async.wait_group %0;" :: "n"(n) : "memory")

__device__ __forceinline__ void ldsm_x4(uint32_t r[4], uint32_t addr) {
    asm volatile("ldmatrix.sync.aligned.m8n8.x4.shared.b16 {%0,%1,%2,%3}, [%4];"
                 : "=r"(r[0]), "=r"(r[1]), "=r"(r[2]), "=r"(r[3])
                 : "r"(addr));
}
__device__ __forceinline__ void mma_f16(float c[4], const uint32_t a[4],
                                        const uint32_t b[2]) {
    asm volatile(
        "mma.sync.aligned.m16n8k16.row.col.f32.f16.f16.f32 "
        "{%0,%1,%2,%3}, {%4,%5,%6,%7}, {%8,%9}, {%0,%1,%2,%3};"
        : "+f"(c[0]), "+f"(c[1]), "+f"(c[2]), "+f"(c[3])
        : "r"(a[0]), "r"(a[1]), "r"(a[2]), "r"(a[3]),
          "r"(b[0]), "r"(b[1]));
}
__device__ __forceinline__ uint32_t pack_h2(float lo, float hi) {
    __half2 h = __floats2half2_rn(lo, hi);
    return *(uint32_t*)&h;
}
// single-MUFU exp2 (EX2.approx)
__device__ __forceinline__ float ex2(float x) {
    float r;
    asm("ex2.approx.f32 %0, %1;" : "=f"(r) : "f"(x));
    return r;
}

// ---------------------------------------------------------------------------
// Kernel 0: fused prep — fp32->fp16 converts + RPE bias (pre-scaled by log2e)
// ---------------------------------------------------------------------------
__global__ void prep_kernel(const float* __restrict__ x,
                            const float* __restrict__ w,
                            const float* __restrict__ ow,
                            const float* __restrict__ rel_pos,
                            const float* __restrict__ rpe_w,
                            __half* __restrict__ xh,
                            __half* __restrict__ wh,
                            __half* __restrict__ owh) {
    if (blockIdx.x < 8192) {
        int u = blockIdx.x * blockDim.x + threadIdx.x;
        const float* src;
        __half* dst;
        int idx;
        if (u < 1048576)       { src = x;  dst = xh;  idx = u; }
        else if (u < 1835008)  { src = w;  dst = wh;  idx = u - 1048576; }
        else                   { src = ow; dst = owh; idx = u - 1835008; }
        int i = idx * 4;
        float4 v = *(const float4*)(src + i);
        uint2 o;
        o.x = pack_h2(v.x, v.y);
        o.y = pack_h2(v.z, v.w);
        *(uint2*)&dst[i] = o;
    } else {
        int wid = threadIdx.x >> 5, lane = threadIdx.x & 31;
        int j = (blockIdx.x - 8192) * 8 + wid;
        if (j >= NBIAS) return;
        float v = rel_pos[j * HDv + lane] * rpe_w[lane]
                + rel_pos[j * HDv + 32 + lane] * rpe_w[32 + lane];
        #pragma unroll
        for (int o = 16; o > 0; o >>= 1) v += __shfl_xor_sync(0xffffffffu, v, o);
        if (lane == 0) g_bias[j] = v * 1.44269504f;   // * log2(e)
    }
}

// ---------------------------------------------------------------------------
// fp16 mma.sync GEMM — ILP-oriented: 4 warps, 64x64 warp tiles.
// CTA tile 128x128, BK=64 halfs, 3-stage cp.async ring, ONE sync/chunk.
// 128 threads, launch_bounds(128,2) -> reg cap 256 (frag double-buffering).
// ---------------------------------------------------------------------------
#define BKH    64
#define PAG    36
#define TILEU  (128 * PAG)
#define STGU   (2 * TILEU)
#define GNSTG  3
#define GSM_B  (GNSTG * STGU * 4)      // 110592 bytes

template<int MODE>
__global__ void __launch_bounds__(128, 2)
f16_gemm(const __half* __restrict__ A, const __half* __restrict__ W,
         const float* __restrict__ bias, float* __restrict__ Cf,
         __half* __restrict__ qh, __half* __restrict__ kh,
         __half* __restrict__ vT, int M, int N, int K) {
    extern __shared__ uint32_t smu[];
    const uint32_t sbase = smem_u32(smu);
    const int tid  = threadIdx.x;
    const int wid  = tid >> 5;
    const int lane = tid & 31;
    const int q    = lane >> 2;
    const int t    = lane & 3;
    const int warp_m = wid >> 1;       // 0..1
    const int warp_n = wid & 1;        // 0..1
    const int bm = blockIdx.y * 128;
    const int bn = blockIdx.x * 128;
    const int nchunk = K / BKH;        // 16

    const int lr   = lane & 15;
    const int lc   = (lane >> 4) * 4;
    const int brow = (lane & 7) | ((lane >> 4) << 3);
    const int bsub = ((lane >> 3) & 1) * 4;

    float acc[4][8][4];
    #pragma unroll
    for (int mi = 0; mi < 4; ++mi)
        #pragma unroll
        for (int ni = 0; ni < 8; ++ni)
            #pragma unroll
            for (int e = 0; e < 4; ++e) acc[mi][ni][e] = 0.f;

    auto load_chunk = [&](int c, int s) {
        const uint32_t ab = sbase + s * (STGU * 4);
        const uint32_t bb = ab + TILEU * 4;
        #pragma unroll
        for (int i = 0; i < 8; ++i) {
            int idx = tid + 128 * i;       // 0..1023
            int row = idx >> 3;            // 0..127
            int cc  = idx & 7;
            uint32_t doff = (uint32_t)(row * PAG + cc * 4) * 4;
            cp_async16(ab + doff, A + (size_t)(bm + row) * K + c * BKH + cc * 8);
            cp_async16(bb + doff, W + (size_t)(bn + row) * K + c * BKH + cc * 8);
        }
    };

    load_chunk(0, 0); CP_COMMIT();
    load_chunk(1, 1); CP_COMMIT();

    uint32_t a_base[4], b_base[4];
    #pragma unroll
    for (int mi = 0; mi < 4; ++mi)
        a_base[mi] = sbase + (uint32_t)((warp_m * 64 + mi * 16 + lr) * PAG + lc) * 4;
    #pragma unroll
    for (int p = 0; p < 4; ++p)
        b_base[p] = sbase + (uint32_t)(TILEU + (warp_n * 64 + p * 16 + brow) * PAG + bsub) * 4;

    int s = 0, sl = 2;
    for (int c = 0; c < nchunk; ++c) {
        if (c + 1 < nchunk) { CP_WAIT(1); } else { CP_WAIT(0); }
        __syncthreads();

        if (c + 2 < nchunk) load_chunk(c + 2, sl);
        CP_COMMIT();

        const uint32_t soff = (uint32_t)(s * STGU * 4);
        #pragma unroll
        for (int ks = 0; ks < 4; ++ks) {
            const uint32_t ko = soff + ks * 32;
            uint32_t af[4][4], bq[4][4];
            #pragma unroll
            for (int mi = 0; mi < 4; ++mi) ldsm_x4(af[mi], a_base[mi] + ko);
            #pragma unroll
            for (int p = 0; p < 4; ++p)   ldsm_x4(bq[p], b_base[p] + ko);
            #pragma unroll
            for (int mi = 0; mi < 4; ++mi)
                #pragma unroll
                for (int ni = 0; ni < 8; ++ni)
                    mma_f16(acc[mi][ni], af[mi], &bq[ni >> 1][(ni & 1) * 2]);
        }

        s  = (s  == 2) ? 0 : s  + 1;
        sl = (sl == 2) ? 0 : sl + 1;
    }

    #pragma unroll
    for (int mi = 0; mi < 4; ++mi) {
        const int row0 = bm + warp_m * 64 + mi * 16 + q;
        #pragma unroll
        for (int ni = 0; ni < 8; ++ni) {
            const int col = bn + warp_n * 64 + ni * 8 + 2 * t;
            const float b0 = bias[col], b1 = bias[col + 1];
            float o00 = acc[mi][ni][0] + b0, o01 = acc[mi][ni][1] + b1;
            float o10 = acc[mi][ni][2] + b0, o11 = acc[mi][ni][3] + b1;
            if (MODE == 0) {
                *(float2*)&Cf[(size_t)row0 * N + col] = make_float2(o00, o01);
                *(float2*)&Cf[(size_t)(row0 + 8) * N + col] = make_float2(o10, o11);
            } else {
                if (bn < 2048) {
                    __half* dst = (bn < 1024) ? qh : kh;
                    int coln = (bn < 1024) ? col : col - 1024;
                    *(uint32_t*)&dst[(size_t)row0 * 1024 + coln] = pack_h2(o00, o01);
                    *(uint32_t*)&dst[(size_t)(row0 + 8) * 1024 + coln] = pack_h2(o10, o11);
                } else {
                    int hd = col - 2048;
                    int h = hd >> 6, d = hd & 63;
                    int bb = row0 >> 11, token = row0 & 2047;
                    __half* base = vT + ((size_t)((bb * 16 + h) * 64 + d)) * 2048 + token;
                    base[0]        = __float2half_rn(o00);
                    base[2048]     = __float2half_rn(o01);
                    base[8]        = __float2half_rn(o10);
                    base[2048 + 8] = __float2half_rn(o11);
                }
            }
        }
    }
}

// ---------------------------------------------------------------------------
// Kernel 3: flash attention with RPE, fp16 mma + ldmatrix (unchanged R14).
// 4 warps x 32 q-rows; KT=64; 2-stage K/V ring; 3 CTAs/SM; max-free softmax.
// ---------------------------------------------------------------------------
#define QT    128
#define KT    64
#define QPA   36
#define VPA   36
#define OFF_Q   0
#define OFF_K   (OFF_Q + QT * QPA)
#define OFF_V   (OFF_K + 2 * KT * QPA)
#define OFF_BW  (OFF_V + 2 * HDv * VPA)
#define FSMU    (OFF_BW + 2 * 192)
#define FSM_B   (FSMU * 4)               // 56832 bytes

__global__ void __launch_bounds__(128, 3)
flash_rpe_f16() {
    extern __shared__ uint32_t smu[];
    const uint32_t sb = smem_u32(smu);
    float* smf = (float*)smu;
    const int b = blockIdx.z, h = blockIdx.y;
    const int qbase = blockIdx.x * QT;
    const int tid = threadIdx.x, wid = tid >> 5, lane = tid & 31;
    const int q = lane >> 2, t = lane & 3;
    const int mb = wid * 32;
    const float scale2 = 0.125f * 1.44269504f;

    const int lr   = lane & 15;
    const int lc   = (lane >> 4) * 4;
    const int brow = (lane & 7) | ((lane >> 4) << 3);
    const int bsub = ((lane >> 3) & 1) * 4;

    #pragma unroll
    for (int i = 0; i < 8; ++i) {
        int idx = tid + 128 * i;
        int row = idx >> 3;
        int c8  = idx & 7;
        cp_async16(sb + (uint32_t)(OFF_Q + row * QPA + c8 * 4) * 4,
                   g_qh + (size_t)(b * Tv + qbase + row) * 1024 + h * 64 + c8 * 8);
    }

    auto load_kv = [&](int kt, int s) {
        const int kbase = kt * KT;
        const uint32_t kb = sb + (uint32_t)(OFF_K + s * KT * QPA) * 4;
        const uint32_t vb = sb + (uint32_t)(OFF_V + s * HDv * VPA) * 4;
        #pragma unroll
        for (int i = 0; i < 4; ++i) {
            int idx = tid + 128 * i;
            int row = idx >> 3;
            int c8  = idx & 7;
            cp_async16(kb + (uint32_t)(row * QPA + c8 * 4) * 4,
                       g_kh + (size_t)(b * Tv + kbase + row) * 1024 + h * 64 + c8 * 8);
            cp_async16(vb + (uint32_t)(row * VPA + c8 * 4) * 4,
                       g_vT + (size_t)((b * 16 + h) * 64 + row) * 2048 + kbase + c8 * 8);
        }
        if (tid < 48) {
            int base = kbase - qbase + 1920;
            cp_async16(sb + (uint32_t)(OFF_BW + s * 192 + tid * 4) * 4,
                       &g_bias[base + tid * 4]);
        }
    };

    load_kv(0, 0); CP_COMMIT();
    load_kv(1, 1); CP_COMMIT();

    uint32_t q_base[2];
    #pragma unroll
    for (int mt = 0; mt < 2; ++mt)
        q_base[mt] = sb + (uint32_t)(OFF_Q + (mb + mt * 16 + lr) * QPA + lc) * 4;
    uint32_t k_base[4], v_base[4];
    #pragma unroll
    for (int p = 0; p < 4; ++p) {
        k_base[p] = sb + (uint32_t)(OFF_K + (p * 16 + brow) * QPA + bsub) * 4;
        v_base[p] = sb + (uint32_t)(OFF_V + (p * 16 + brow) * VPA + bsub) * 4;
    }

    float l[4] = {0.f, 0.f, 0.f, 0.f};
    float ao[2][8][4];
    #pragma unroll
    for (int mt = 0; mt < 2; ++mt)
        #pragma unroll
        for (int ni = 0; ni < 8; ++ni)
            #pragma unroll
            for (int e = 0; e < 4; ++e) ao[mt][ni][e] = 0.f;

    const int NIT = Tv / KT;   // 32
    for (int kt = 0; kt < NIT; ++kt) {
        const int s = kt & 1;
        if (kt < NIT - 1) { CP_WAIT(1); } else { CP_WAIT(0); }
        __syncthreads();

        const uint32_t ksoff = (uint32_t)(s * KT * QPA * 4);
        const uint32_t vsoff = (uint32_t)(s * HDv * VPA * 4);
        const float* bw = smf + OFF_BW + s * 192;

        float as_[2][8][4];
        #pragma unroll
        for (int mt = 0; mt < 2; ++mt)
            #pragma unroll
            for (int ni = 0; ni < 8; ++ni)
                #pragma unroll
                for (int e = 0; e < 4; ++e) as_[mt][ni][e] = 0.f;

        #pragma unroll
        for (int ks = 0; ks < 4; ++ks) {
            const uint32_t ko = ks * 32;
            uint32_t af0[4], af1[4];
            ldsm_x4(af0, q_base[0] + ko);
            ldsm_x4(af1, q_base[1] + ko);
            #pragma unroll
            for (int p = 0; p < 4; ++p) {
                uint32_t kq[4];
                ldsm_x4(kq, k_base[p] + ksoff + ko);
                mma_f16(as_[0][2 * p],     af0, &kq[0]);
                mma_f16(as_[0][2 * p + 1], af0, &kq[2]);
                mma_f16(as_[1][2 * p],     af1, &kq[0]);
                mma_f16(as_[1][2 * p + 1], af1, &kq[2]);
            }
        }

        uint32_t pf[2][8][2];
        #pragma unroll
        for (int mt = 0; mt < 2; ++mt) {
            const int rowb = mb + mt * 16;
            float rs0 = 0.f, rs1 = 0.f;
            #pragma unroll
            for (int ni = 0; ni < 8; ++ni) {
                const int i0 = ni * 8 + 2 * t - rowb - q + 127;
                float p0 = ex2(fmaf(as_[mt][ni][0], scale2, bw[i0]));
                float p1 = ex2(fmaf(as_[mt][ni][1], scale2, bw[i0 + 1]));
                float p2 = ex2(fmaf(as_[mt][ni][2], scale2, bw[i0 - 8]));
                float p3 = ex2(fmaf(as_[mt][ni][3], scale2, bw[i0 - 7]));
                rs0 += p0 + p1; rs1 += p2 + p3;
                pf[mt][ni][0] = pack_h2(p0, p1);
                pf[mt][ni][1] = pack_h2(p2, p3);
            }
            l[2 * mt]     += rs0;
            l[2 * mt + 1] += rs1;
        }

        #pragma unroll
        for (int ks = 0; ks < 4; ++ks) {
            const uint32_t ko = ks * 32;
            uint32_t a0[4], a1[4];
            a0[0] = pf[0][2 * ks][0];     a0[1] = pf[0][2 * ks][1];
            a0[2] = pf[0][2 * ks + 1][0]; a0[3] = pf[0][2 * ks + 1][1];
            a1[0] = pf[1][2 * ks][0];     a1[1] = pf[1][2 * ks][1];
            a1[2] = pf[1][2 * ks + 1][0]; a1[3] = pf[1][2 * ks + 1][1];
            #pragma unroll
            for (int p = 0; p < 4; ++p) {
                uint32_t vq[4];
                ldsm_x4(vq, v_base[p] + vsoff + ko);
                mma_f16(ao[0][2 * p],     a0, &vq[0]);
                mma_f16(ao[0][2 * p + 1], a0, &vq[2]);
                mma_f16(ao[1][2 * p],     a1, &vq[0]);
                mma_f16(ao[1][2 * p + 1], a1, &vq[2]);
            }
        }

        __syncthreads();
        if (kt + 2 < NIT) { load_kv(kt + 2, s); CP_COMMIT(); }
    }

    #pragma unroll
    for (int i = 0; i < 4; ++i) {
        #pragma unroll
        for (int off = 1; off <= 2; off <<= 1)
            l[i] += __shfl_xor_sync(0xffffffffu, l[i], off);
    }
    #pragma unroll
    for (int mt = 0; mt < 2; ++mt) {
        const float inv0 = 1.f / l[2 * mt];
        const float inv1 = 1.f / l[2 * mt + 1];
        const int r0 = qbase + mb + mt * 16 + q;
        #pragma unroll
        for (int ni = 0; ni < 8; ++ni) {
            const int col = h * HDv + ni * 8 + 2 * t;
            *(uint32_t*)&g_attnh[(size_t)(b * Tv + r0) * Dv + col]
                = pack_h2(ao[mt][ni][0] * inv0, ao[mt][ni][1] * inv0);
            *(uint32_t*)&g_attnh[(size_t)(b * Tv + r0 + 8) * Dv + col]
                = pack_h2(ao[mt][ni][2] * inv1, ao[mt][ni][3] * inv1);
        }
    }
}

// ---------------------------------------------------------------------------
// Launcher
// ---------------------------------------------------------------------------
extern "C" void kernel_launch(void* const* d_in, const int* in_sizes, int n_in,
                              void* d_out, int out_size) {
    const float* x       = (const float*)d_in[0];
    const float* qkv_w   = (const float*)d_in[1];
    const float* qkv_b   = (const float*)d_in[2];
    const float* out_w   = (const float*)d_in[3];
    const float* out_b   = (const float*)d_in[4];
    const float* rel_pos = (const float*)d_in[5];
    const float* rpe_w   = (const float*)d_in[6];
    float* out = (float*)d_out;

    __half *xh, *wh, *owh, *qh, *kh, *vT, *attnh;
    cudaGetSymbolAddress((void**)&xh,    g_xh);
    cudaGetSymbolAddress((void**)&wh,    g_wh);
    cudaGetSymbolAddress((void**)&owh,   g_owh);
    cudaGetSymbolAddress((void**)&qh,    g_qh);
    cudaGetSymbolAddress((void**)&kh,    g_kh);
    cudaGetSymbolAddress((void**)&vT,    g_vT);
    cudaGetSymbolAddress((void**)&attnh, g_attnh);

    cudaFuncSetAttribute(f16_gemm<0>,
                         cudaFuncAttributeMaxDynamicSharedMemorySize, GSM_B);
    cudaFuncSetAttribute(f16_gemm<1>,
                         cudaFuncAttributeMaxDynamicSharedMemorySize, GSM_B);
    cudaFuncSetAttribute(flash_rpe_f16,
                         cudaFuncAttributeMaxDynamicSharedMemorySize, FSM_B);

    // 0) fused converts + RPE bias projection (bias pre-scaled by log2e)
    prep_kernel<<<8704, 256>>>(x, qkv_w, out_w, rel_pos, rpe_w, xh, wh, owh);

    // 1) QKV projection -> Q,K (half) + V transposed (half)
    {
        dim3 grid(3 * Dv / 128, BT / 128);
        f16_gemm<1><<<grid, 128, GSM_B>>>(xh, wh, qkv_b, nullptr,
                                          qh, kh, vT, BT, 3 * Dv, Dv);
    }

    // 2) flash attention with RPE (max-free ex2 softmax)
    {
        dim3 grid(Tv / QT, Hv, Bv);
        flash_rpe_f16<<<grid, 128, FSM_B>>>();
    }

    // 3) output projection -> fp32 out
    {
        dim3 grid(Dv / 128, BT / 128);
        f16_gemm<0><<<grid, 128, GSM_B>>>(attnh, owh, out_b, out,
                                          nullptr, nullptr, nullptr,
                                          BT, Dv, Dv);
    }
}

// round 16
// speedup vs baseline: 1.1326x; 1.0438x over previous
#include <cuda_runtime.h>
#include <cuda_fp16.h>
#include <math.h>
#include <stdint.h>

// Problem constants
#define Bv      2
#define Tv      2048
#define Dv      1024
#define Hv      16
#define HDv     64
#define MAXLEN  2048
#define NBIAS   (2 * MAXLEN - 1)   // 4095
#define BT      (Bv * Tv)          // 4096

// ---------------------------------------------------------------------------
// Scratch (device globals)
// ---------------------------------------------------------------------------
__device__ float  g_bias[4608];             // projected RPE bias * log2(e)
__device__ __half g_xh[BT * Dv];            // x      (half)
__device__ __half g_wh[3 * Dv * Dv];        // qkv_w  (half)
__device__ __half g_owh[Dv * Dv];           // out_w  (half)
__device__ __half g_qh[BT * Dv];            // Q      [b*T+t][h*64+d]
__device__ __half g_kh[BT * Dv];            // K      [b*T+t][h*64+d]
__device__ __half g_vT[Bv * Hv * HDv * Tv]; // V^T  [(b*16+h)*64+d][token]
__device__ __half g_attnh[BT * Dv];         // attention output (half)
// split-KV partials
__device__ float  g_po0[BT * Dv];           // unnormalized O, kv-half 0 (16MB)
__device__ float  g_po1[BT * Dv];           // unnormalized O, kv-half 1 (16MB)
__device__ float  g_pl0[Bv * Hv * Tv];      // l partial, half 0
__device__ float  g_pl1[Bv * Hv * Tv];      // l partial, half 1

// ---------------------------------------------------------------------------
// PTX helpers (sm_103-base safe: cp.async + mma.sync + ldmatrix)
// ---------------------------------------------------------------------------
__device__ __forceinline__ uint32_t smem_u32(const void* p) {
    uint32_t a;
    asm("{ .reg .u64 t; cvta.to.shared.u64 t, %1; cvt.u32.u64 %0, t; }"
        : "=r"(a) : "l"(p));
    return a;
}
__device__ __forceinline__ void cp_async16(uint32_t saddr, const void* gptr) {
    asm volatile("cp.async.cg.shared.global [%0], [%1], 16;"
                 :: "r"(saddr), "l"(gptr) : "memory");
}
#define CP_COMMIT() asm volatile("cp.async.commit_group;" ::: "memory")
#define CP_WAIT(n)  asm volatile("cp.async.wait_group %0;" :: "n"(n) : "memory")

__device__ __forceinline__ void ldsm_x4(uint32_t r[4], uint32_t addr) {
    asm volatile("ldmatrix.sync.aligned.m8n8.x4.shared.b16 {%0,%1,%2,%3}, [%4];"
                 : "=r"(r[0]), "=r"(r[1]), "=r"(r[2]), "=r"(r[3])
                 : "r"(addr));
}
__device__ __forceinline__ void mma_f16(float c[4], const uint32_t a[4],
                                        const uint32_t b[2]) {
    asm volatile(
        "mma.sync.aligned.m16n8k16.row.col.f32.f16.f16.f32 "
        "{%0,%1,%2,%3}, {%4,%5,%6,%7}, {%8,%9}, {%0,%1,%2,%3};"
        : "+f"(c[0]), "+f"(c[1]), "+f"(c[2]), "+f"(c[3])
        : "r"(a[0]), "r"(a[1]), "r"(a[2]), "r"(a[3]),
          "r"(b[0]), "r"(b[1]));
}
__device__ __forceinline__ uint32_t pack_h2(float lo, float hi) {
    __half2 h = __floats2half2_rn(lo, hi);
    return *(uint32_t*)&h;
}
// single-MUFU exp2 (EX2.approx)
__device__ __forceinline__ float ex2(float x) {
    float r;
    asm("ex2.approx.f32 %0, %1;" : "=f"(r) : "f"(x));
    return r;
}

// ---------------------------------------------------------------------------
// Kernel 0: fused prep — fp32->fp16 converts + RPE bias (pre-scaled by log2e)
// ---------------------------------------------------------------------------
__global__ void prep_kernel(const float* __restrict__ x,
                            const float* __restrict__ w,
                            const float* __restrict__ ow,
                            const float* __restrict__ rel_pos,
                            const float* __restrict__ rpe_w,
                            __half* __restrict__ xh,
                            __half* __restrict__ wh,
                            __half* __restrict__ owh) {
    if (blockIdx.x < 8192) {
        int u = blockIdx.x * blockDim.x + threadIdx.x;
        const float* src;
        __half* dst;
        int idx;
        if (u < 1048576)       { src = x;  dst = xh;  idx = u; }
        else if (u < 1835008)  { src = w;  dst = wh;  idx = u - 1048576; }
        else                   { src = ow; dst = owh; idx = u - 1835008; }
        int i = idx * 4;
        float4 v = *(const float4*)(src + i);
        uint2 o;
        o.x = pack_h2(v.x, v.y);
        o.y = pack_h2(v.z, v.w);
        *(uint2*)&dst[i] = o;
    } else {
        int wid = threadIdx.x >> 5, lane = threadIdx.x & 31;
        int j = (blockIdx.x - 8192) * 8 + wid;
        if (j >= NBIAS) return;
        float v = rel_pos[j * HDv + lane] * rpe_w[lane]
                + rel_pos[j * HDv + 32 + lane] * rpe_w[32 + lane];
        #pragma unroll
        for (int o = 16; o > 0; o >>= 1) v += __shfl_xor_sync(0xffffffffu, v, o);
        if (lane == 0) g_bias[j] = v * 1.44269504f;   // * log2(e)
    }
}

// ---------------------------------------------------------------------------
// fp16 mma.sync GEMM — 4 warps, 64x64 warp tiles, 3-stage ring (R15 config).
// ---------------------------------------------------------------------------
#define BKH    64
#define PAG    36
#define TILEU  (128 * PAG)
#define STGU   (2 * TILEU)
#define GNSTG  3
#define GSM_B  (GNSTG * STGU * 4)      // 110592 bytes

template<int MODE>
__global__ void __launch_bounds__(128, 2)
f16_gemm(const __half* __restrict__ A, const __half* __restrict__ W,
         const float* __restrict__ bias, float* __restrict__ Cf,
         __half* __restrict__ qh, __half* __restrict__ kh,
         __half* __restrict__ vT, int M, int N, int K) {
    extern __shared__ uint32_t smu[];
    const uint32_t sbase = smem_u32(smu);
    const int tid  = threadIdx.x;
    const int wid  = tid >> 5;
    const int lane = tid & 31;
    const int q    = lane >> 2;
    const int t    = lane & 3;
    const int warp_m = wid >> 1;
    const int warp_n = wid & 1;
    const int bm = blockIdx.y * 128;
    const int bn = blockIdx.x * 128;
    const int nchunk = K / BKH;

    const int lr   = lane & 15;
    const int lc   = (lane >> 4) * 4;
    const int brow = (lane & 7) | ((lane >> 4) << 3);
    const int bsub = ((lane >> 3) & 1) * 4;

    float acc[4][8][4];
    #pragma unroll
    for (int mi = 0; mi < 4; ++mi)
        #pragma unroll
        for (int ni = 0; ni < 8; ++ni)
            #pragma unroll
            for (int e = 0; e < 4; ++e) acc[mi][ni][e] = 0.f;

    auto load_chunk = [&](int c, int s) {
        const uint32_t ab = sbase + s * (STGU * 4);
        const uint32_t bb = ab + TILEU * 4;
        #pragma unroll
        for (int i = 0; i < 8; ++i) {
            int idx = tid + 128 * i;
            int row = idx >> 3;
            int cc  = idx & 7;
            uint32_t doff = (uint32_t)(row * PAG + cc * 4) * 4;
            cp_async16(ab + doff, A + (size_t)(bm + row) * K + c * BKH + cc * 8);
            cp_async16(bb + doff, W + (size_t)(bn + row) * K + c * BKH + cc * 8);
        }
    };

    load_chunk(0, 0); CP_COMMIT();
    load_chunk(1, 1); CP_COMMIT();

    uint32_t a_base[4], b_base[4];
    #pragma unroll
    for (int mi = 0; mi < 4; ++mi)
        a_base[mi] = sbase + (uint32_t)((warp_m * 64 + mi * 16 + lr) * PAG + lc) * 4;
    #pragma unroll
    for (int p = 0; p < 4; ++p)
        b_base[p] = sbase + (uint32_t)(TILEU + (warp_n * 64 + p * 16 + brow) * PAG + bsub) * 4;

    int s = 0, sl = 2;
    for (int c = 0; c < nchunk; ++c) {
        if (c + 1 < nchunk) { CP_WAIT(1); } else { CP_WAIT(0); }
        __syncthreads();

        if (c + 2 < nchunk) load_chunk(c + 2, sl);
        CP_COMMIT();

        const uint32_t soff = (uint32_t)(s * STGU * 4);
        #pragma unroll
        for (int ks = 0; ks < 4; ++ks) {
            const uint32_t ko = soff + ks * 32;
            uint32_t af[4][4], bq[4][4];
            #pragma unroll
            for (int mi = 0; mi < 4; ++mi) ldsm_x4(af[mi], a_base[mi] + ko);
            #pragma unroll
            for (int p = 0; p < 4; ++p)   ldsm_x4(bq[p], b_base[p] + ko);
            #pragma unroll
            for (int mi = 0; mi < 4; ++mi)
                #pragma unroll
                for (int ni = 0; ni < 8; ++ni)
                    mma_f16(acc[mi][ni], af[mi], &bq[ni >> 1][(ni & 1) * 2]);
        }

        s  = (s  == 2) ? 0 : s  + 1;
        sl = (sl == 2) ? 0 : sl + 1;
    }

    #pragma unroll
    for (int mi = 0; mi < 4; ++mi) {
        const int row0 = bm + warp_m * 64 + mi * 16 + q;
        #pragma unroll
        for (int ni = 0; ni < 8; ++ni) {
            const int col = bn + warp_n * 64 + ni * 8 + 2 * t;
            const float b0 = bias[col], b1 = bias[col + 1];
            float o00 = acc[mi][ni][0] + b0, o01 = acc[mi][ni][1] + b1;
            float o10 = acc[mi][ni][2] + b0, o11 = acc[mi][ni][3] + b1;
            if (MODE == 0) {
                *(float2*)&Cf[(size_t)row0 * N + col] = make_float2(o00, o01);
                *(float2*)&Cf[(size_t)(row0 + 8) * N + col] = make_float2(o10, o11);
            } else {
                if (bn < 2048) {
                    __half* dst = (bn < 1024) ? qh : kh;
                    int coln = (bn < 1024) ? col : col - 1024;
                    *(uint32_t*)&dst[(size_t)row0 * 1024 + coln] = pack_h2(o00, o01);
                    *(uint32_t*)&dst[(size_t)(row0 + 8) * 1024 + coln] = pack_h2(o10, o11);
                } else {
                    int hd = col - 2048;
                    int h = hd >> 6, d = hd & 63;
                    int bb = row0 >> 11, token = row0 & 2047;
                    __half* base = vT + ((size_t)((bb * 16 + h) * 64 + d)) * 2048 + token;
                    base[0]        = __float2half_rn(o00);
                    base[2048]     = __float2half_rn(o01);
                    base[8]        = __float2half_rn(o10);
                    base[2048 + 8] = __float2half_rn(o11);
                }
            }
        }
    }
}

// ---------------------------------------------------------------------------
// Kernel 3: flash attention, SPLIT-KV (2 halves). Each CTA handles 16 of 32
// KT-iterations; writes unnormalized fp32 O-partial + l-partial. Max-free
// softmax makes the merge a plain sum. 4 warps x 32 q-rows; 3 CTAs/SM.
// ---------------------------------------------------------------------------
#define QT    128
#define KT    64
#define QPA   36
#define VPA   36
#define OFF_Q   0
#define OFF_K   (OFF_Q + QT * QPA)
#define OFF_V   (OFF_K + 2 * KT * QPA)
#define OFF_BW  (OFF_V + 2 * HDv * VPA)
#define FSMU    (OFF_BW + 2 * 192)
#define FSM_B   (FSMU * 4)               // 56832 bytes
#define NITH    16                       // iterations per kv-half

__global__ void __launch_bounds__(128, 3)
flash_rpe_f16() {
    extern __shared__ uint32_t smu[];
    const uint32_t sb = smem_u32(smu);
    float* smf = (float*)smu;
    const int b   = blockIdx.z >> 1;
    const int kvh = blockIdx.z & 1;
    const int h = blockIdx.y;
    const int qbase = blockIdx.x * QT;
    const int tid = threadIdx.x, wid = tid >> 5, lane = tid & 31;
    const int q = lane >> 2, t = lane & 3;
    const int mb = wid * 32;
    const float scale2 = 0.125f * 1.44269504f;

    const int lr   = lane & 15;
    const int lc   = (lane >> 4) * 4;
    const int brow = (lane & 7) | ((lane >> 4) << 3);
    const int bsub = ((lane >> 3) & 1) * 4;

    #pragma unroll
    for (int i = 0; i < 8; ++i) {
        int idx = tid + 128 * i;
        int row = idx >> 3;
        int c8  = idx & 7;
        cp_async16(sb + (uint32_t)(OFF_Q + row * QPA + c8 * 4) * 4,
                   g_qh + (size_t)(b * Tv + qbase + row) * 1024 + h * 64 + c8 * 8);
    }

    auto load_kv = [&](int kt, int s) {     // kt is GLOBAL iteration index
        const int kbase = kt * KT;
        const uint32_t kb = sb + (uint32_t)(OFF_K + s * KT * QPA) * 4;
        const uint32_t vb = sb + (uint32_t)(OFF_V + s * HDv * VPA) * 4;
        #pragma unroll
        for (int i = 0; i < 4; ++i) {
            int idx = tid + 128 * i;
            int row = idx >> 3;
            int c8  = idx & 7;
            cp_async16(kb + (uint32_t)(row * QPA + c8 * 4) * 4,
                       g_kh + (size_t)(b * Tv + kbase + row) * 1024 + h * 64 + c8 * 8);
            cp_async16(vb + (uint32_t)(row * VPA + c8 * 4) * 4,
                       g_vT + (size_t)((b * 16 + h) * 64 + row) * 2048 + kbase + c8 * 8);
        }
        if (tid < 48) {
            int base = kbase - qbase + 1920;
            cp_async16(sb + (uint32_t)(OFF_BW + s * 192 + tid * 4) * 4,
                       &g_bias[base + tid * 4]);
        }
    };

    const int kt0 = kvh * NITH;
    load_kv(kt0 + 0, 0); CP_COMMIT();
    load_kv(kt0 + 1, 1); CP_COMMIT();

    uint32_t q_base[2];
    #pragma unroll
    for (int mt = 0; mt < 2; ++mt)
        q_base[mt] = sb + (uint32_t)(OFF_Q + (mb + mt * 16 + lr) * QPA + lc) * 4;
    uint32_t k_base[4], v_base[4];
    #pragma unroll
    for (int p = 0; p < 4; ++p) {
        k_base[p] = sb + (uint32_t)(OFF_K + (p * 16 + brow) * QPA + bsub) * 4;
        v_base[p] = sb + (uint32_t)(OFF_V + (p * 16 + brow) * VPA + bsub) * 4;
    }

    float l[4] = {0.f, 0.f, 0.f, 0.f};
    float ao[2][8][4];
    #pragma unroll
    for (int mt = 0; mt < 2; ++mt)
        #pragma unroll
        for (int ni = 0; ni < 8; ++ni)
            #pragma unroll
            for (int e = 0; e < 4; ++e) ao[mt][ni][e] = 0.f;

    for (int it = 0; it < NITH; ++it) {
        const int s = it & 1;
        if (it < NITH - 1) { CP_WAIT(1); } else { CP_WAIT(0); }
        __syncthreads();

        const uint32_t ksoff = (uint32_t)(s * KT * QPA * 4);
        const uint32_t vsoff = (uint32_t)(s * HDv * VPA * 4);
        const float* bw = smf + OFF_BW + s * 192;

        float as_[2][8][4];
        #pragma unroll
        for (int mt = 0; mt < 2; ++mt)
            #pragma unroll
            for (int ni = 0; ni < 8; ++ni)
                #pragma unroll
                for (int e = 0; e < 4; ++e) as_[mt][ni][e] = 0.f;

        #pragma unroll
        for (int ks = 0; ks < 4; ++ks) {
            const uint32_t ko = ks * 32;
            uint32_t af0[4], af1[4];
            ldsm_x4(af0, q_base[0] + ko);
            ldsm_x4(af1, q_base[1] + ko);
            #pragma unroll
            for (int p = 0; p < 4; ++p) {
                uint32_t kq[4];
                ldsm_x4(kq, k_base[p] + ksoff + ko);
                mma_f16(as_[0][2 * p],     af0, &kq[0]);
                mma_f16(as_[0][2 * p + 1], af0, &kq[2]);
                mma_f16(as_[1][2 * p],     af1, &kq[0]);
                mma_f16(as_[1][2 * p + 1], af1, &kq[2]);
            }
        }

        uint32_t pf[2][8][2];
        #pragma unroll
        for (int mt = 0; mt < 2; ++mt) {
            const int rowb = mb + mt * 16;
            float rs0 = 0.f, rs1 = 0.f;
            #pragma unroll
            for (int ni = 0; ni < 8; ++ni) {
                const int i0 = ni * 8 + 2 * t - rowb - q + 127;
                float p0 = ex2(fmaf(as_[mt][ni][0], scale2, bw[i0]));
                float p1 = ex2(fmaf(as_[mt][ni][1], scale2, bw[i0 + 1]));
                float p2 = ex2(fmaf(as_[mt][ni][2], scale2, bw[i0 - 8]));
                float p3 = ex2(fmaf(as_[mt][ni][3], scale2, bw[i0 - 7]));
                rs0 += p0 + p1; rs1 += p2 + p3;
                pf[mt][ni][0] = pack_h2(p0, p1);
                pf[mt][ni][1] = pack_h2(p2, p3);
            }
            l[2 * mt]     += rs0;
            l[2 * mt + 1] += rs1;
        }

        #pragma unroll
        for (int ks = 0; ks < 4; ++ks) {
            const uint32_t ko = ks * 32;
            uint32_t a0[4], a1[4];
            a0[0] = pf[0][2 * ks][0];     a0[1] = pf[0][2 * ks][1];
            a0[2] = pf[0][2 * ks + 1][0]; a0[3] = pf[0][2 * ks + 1][1];
            a1[0] = pf[1][2 * ks][0];     a1[1] = pf[1][2 * ks][1];
            a1[2] = pf[1][2 * ks + 1][0]; a1[3] = pf[1][2 * ks + 1][1];
            #pragma unroll
            for (int p = 0; p < 4; ++p) {
                uint32_t vq[4];
                ldsm_x4(vq, v_base[p] + vsoff + ko);
                mma_f16(ao[0][2 * p],     a0, &vq[0]);
                mma_f16(ao[0][2 * p + 1], a0, &vq[2]);
                mma_f16(ao[1][2 * p],     a1, &vq[0]);
                mma_f16(ao[1][2 * p + 1], a1, &vq[2]);
            }
        }

        __syncthreads();
        if (it + 2 < NITH) { load_kv(kt0 + it + 2, s); CP_COMMIT(); }
    }

    // ---- reduce l across the quad; write fp32 partials (no normalization) --
    #pragma unroll
    for (int i = 0; i < 4; ++i) {
        #pragma unroll
        for (int off = 1; off <= 2; off <<= 1)
            l[i] += __shfl_xor_sync(0xffffffffu, l[i], off);
    }
    float* po = kvh ? g_po1 : g_po0;
    float* pl = kvh ? g_pl1 : g_pl0;
    #pragma unroll
    for (int mt = 0; mt < 2; ++mt) {
        const int r0 = qbase + mb + mt * 16 + q;
        if (t == 0) {
            pl[(b * 16 + h) * Tv + r0]     = l[2 * mt];
            pl[(b * 16 + h) * Tv + r0 + 8] = l[2 * mt + 1];
        }
        #pragma unroll
        for (int ni = 0; ni < 8; ++ni) {
            const int col = h * HDv + ni * 8 + 2 * t;
            *(float2*)&po[(size_t)(b * Tv + r0) * Dv + col]
                = make_float2(ao[mt][ni][0], ao[mt][ni][1]);
            *(float2*)&po[(size_t)(b * Tv + r0 + 8) * Dv + col]
                = make_float2(ao[mt][ni][2], ao[mt][ni][3]);
        }
    }
}

// ---------------------------------------------------------------------------
// Kernel 4: combine split-KV partials -> half attn
// ---------------------------------------------------------------------------
__global__ void combine_kernel() {
    int u = blockIdx.x * blockDim.x + threadIdx.x;   // 1M units of 4 floats
    int i = u * 4;
    int row = i >> 10;            // global token row (b*T + r)
    int col = i & 1023;
    int h = col >> 6;
    int b = row >> 11;
    int r = row & 2047;
    float l = g_pl0[(b * 16 + h) * Tv + r] + g_pl1[(b * 16 + h) * Tv + r];
    float inv = 1.f / l;
    float4 o0 = *(const float4*)&g_po0[i];
    float4 o1 = *(const float4*)&g_po1[i];
    uint2 o;
    o.x = pack_h2((o0.x + o1.x) * inv, (o0.y + o1.y) * inv);
    o.y = pack_h2((o0.z + o1.z) * inv, (o0.w + o1.w) * inv);
    *(uint2*)&g_attnh[i] = o;
}

// ---------------------------------------------------------------------------
// Launcher
// ---------------------------------------------------------------------------
extern "C" void kernel_launch(void* const* d_in, const int* in_sizes, int n_in,
                              void* d_out, int out_size) {
    const float* x       = (const float*)d_in[0];
    const float* qkv_w   = (const float*)d_in[1];
    const float* qkv_b   = (const float*)d_in[2];
    const float* out_w   = (const float*)d_in[3];
    const float* out_b   = (const float*)d_in[4];
    const float* rel_pos = (const float*)d_in[5];
    const float* rpe_w   = (const float*)d_in[6];
    float* out = (float*)d_out;

    __half *xh, *wh, *owh, *qh, *kh, *vT, *attnh;
    cudaGetSymbolAddress((void**)&xh,    g_xh);
    cudaGetSymbolAddress((void**)&wh,    g_wh);
    cudaGetSymbolAddress((void**)&owh,   g_owh);
    cudaGetSymbolAddress((void**)&qh,    g_qh);
    cudaGetSymbolAddress((void**)&kh,    g_kh);
    cudaGetSymbolAddress((void**)&vT,    g_vT);
    cudaGetSymbolAddress((void**)&attnh, g_attnh);

    cudaFuncSetAttribute(f16_gemm<0>,
                         cudaFuncAttributeMaxDynamicSharedMemorySize, GSM_B);
    cudaFuncSetAttribute(f16_gemm<1>,
                         cudaFuncAttributeMaxDynamicSharedMemorySize, GSM_B);
    cudaFuncSetAttribute(flash_rpe_f16,
                         cudaFuncAttributeMaxDynamicSharedMemorySize, FSM_B);

    // 0) fused converts + RPE bias projection (bias pre-scaled by log2e)
    prep_kernel<<<8704, 256>>>(x, qkv_w, out_w, rel_pos, rpe_w, xh, wh, owh);

    // 1) QKV projection -> Q,K (half) + V transposed (half)
    {
        dim3 grid(3 * Dv / 128, BT / 128);
        f16_gemm<1><<<grid, 128, GSM_B>>>(xh, wh, qkv_b, nullptr,
                                          qh, kh, vT, BT, 3 * Dv, Dv);
    }

    // 2) flash attention, split-KV x2 (max-free ex2 softmax, fp32 partials)
    {
        dim3 grid(Tv / QT, Hv, Bv * 2);
        flash_rpe_f16<<<grid, 128, FSM_B>>>();
    }

    // 2b) combine partials -> half attn
    combine_kernel<<<BT * Dv / 1024, 256>>>();

    // 3) output projection -> fp32 out
    {
        dim3 grid(Dv / 128, BT / 128);
        f16_gemm<0><<<grid, 128, GSM_B>>>(attnh, owh, out_b, out,
                                          nullptr, nullptr, nullptr,
                                          BT, Dv, Dv);
    }
}